// round 14
// baseline (speedup 1.0000x reference)
#include <cuda_runtime.h>
#include <cuda_bf16.h>
#include <cuda_fp16.h>
#include <math.h>
#include <stdint.h>

#define HS    3072
#define MLPD  12288
#define NH    24
#define HD    128
#define LTXT  512
#define LIMG  2048
#define LTOT  2560
#define QKVW  9216
#define NMT   2      // txt M-tiles (512/256)
#define NMALL 10     // total M-tiles (2560/256)

#if defined(__CUDA_ARCH__)
#if defined(__CUDA_ARCH_FEAT_SM103_ALL) || \
    (defined(__CUDA_ARCH_SPECIFIC__) && (__CUDA_ARCH_SPECIFIC__ >= 1000))
#define HAS_TCGEN05 1
#else
#define HAS_TCGEN05 0
#endif
#else
#define HAS_TCGEN05 0
#endif

// ---------------------------------------------------------------------------
// Static device scratch
// ---------------------------------------------------------------------------
__device__ float g_silu[HS];
__device__ float g_mod_img[6 * HS];
__device__ float g_mod_txt[6 * HS];
// A-operand buffers: chunk-major fp16 layout [K/64][LTOT][64], pre-swizzled
__device__ __align__(1024) __half g_x   [(size_t)LTOT * HS];
__device__ __align__(1024) __half g_attn[(size_t)LTOT * HS];
__device__ __align__(1024) __half g_x2  [(size_t)LTOT * HS];
__device__ __align__(1024) __half g_h1  [(size_t)LTOT * MLPD];
// row-major buffers
__device__ __half g_qkv [(size_t)LTOT * QKVW];
__device__ __half g_q   [(size_t)NH * LTOT * HD];   // pre-scaled by FA_SCALE
__device__ __half g_k   [(size_t)NH * LTOT * HD];
__device__ __half g_v   [(size_t)NH * LTOT * HD];
__device__ float  g_x1  [(size_t)LTOT * HS];
// converted weights: chunk-major fp16, pre-swizzled [K/64][N][64]
#define OFF_QKV_T  0u
#define OFF_QKV_I  28311552u
#define OFF_PROJ_T 56623104u
#define OFF_PROJ_I 66060288u
#define OFF_MLP1_T 75497472u
#define OFF_MLP1_I 113246208u
#define OFF_MLP2_T 150994944u
#define OFF_MLP2_I 188743680u
__device__ __align__(1024) __half g_w[226492416];

// ---------------------------------------------------------------------------
// Helpers
// ---------------------------------------------------------------------------
__device__ __forceinline__ float gelu_tanh(float x) {
    float x3 = x * x * x;
    return 0.5f * x * (1.0f + tanhf(0.7978845608028654f * (x + 0.044715f * x3)));
}
__device__ __forceinline__ uint32_t smem_u32(const void* p) {
    uint32_t a;
    asm("{ .reg .u64 t; cvta.to.shared.u64 t, %1; cvt.u32.u64 %0, t; }" : "=r"(a) : "l"(p));
    return a;
}
__device__ __forceinline__ size_t aoff16(int row, int k, int rows) {
    int q = (k >> 3) & 7;
    return ((size_t)(k >> 6) * rows + row) * 64 + (((q ^ (row & 7)) << 3) + (k & 7));
}
__device__ __forceinline__ void mma_f16(float c[4], const unsigned int a[4],
                                        unsigned int b0, unsigned int b1) {
    asm volatile(
        "mma.sync.aligned.m16n8k16.row.col.f32.f16.f16.f32 "
        "{%0,%1,%2,%3}, {%4,%5,%6,%7}, {%8,%9}, {%0,%1,%2,%3};"
        : "+f"(c[0]), "+f"(c[1]), "+f"(c[2]), "+f"(c[3])
        : "r"(a[0]), "r"(a[1]), "r"(a[2]), "r"(a[3]), "r"(b0), "r"(b1));
}

// ---------------------------------------------------------------------------
// Elementwise kernels
// ---------------------------------------------------------------------------
__global__ void silu_kernel(const float* __restrict__ v, float* __restrict__ o) {
    int i = blockIdx.x * 256 + threadIdx.x;
    if (i < HS) { float x = v[i]; o[i] = x / (1.0f + expf(-x)); }
}

__global__ void mod_gemv2(const float* __restrict__ sv, const float* __restrict__ w,
                          const float* __restrict__ b, float* __restrict__ out) {
    __shared__ float ssv[HS];
    __shared__ float red[4][64];
    for (int i = threadIdx.x; i < HS; i += 256) ssv[i] = sv[i];
    __syncthreads();
    const int jl = threadIdx.x & 63, kq = threadIdx.x >> 6;
    const int j = blockIdx.x * 64 + jl;
    const int i0 = kq * (HS / 4);
    float acc = 0.0f;
    #pragma unroll 8
    for (int i = 0; i < HS / 4; i++)
        acc += ssv[i0 + i] * w[(size_t)(i0 + i) * (6 * HS) + j];
    red[kq][jl] = acc;
    __syncthreads();
    if (threadIdx.x < 64) {
        int jj = blockIdx.x * 64 + threadIdx.x;
        out[jj] = red[0][threadIdx.x] + red[1][threadIdx.x] +
                  red[2][threadIdx.x] + red[3][threadIdx.x] + b[jj];
    }
}

// weight conversion: W [K,N] row-major fp32 -> chunk-major fp16 pre-swizzled.
// Grid (N/256, K/16): each block covers a quarter of a 64-k chunk.
__global__ void conv_w(const float* __restrict__ W, __half* __restrict__ Wc, int N) {
    const int n = blockIdx.x * 256 + threadIdx.x;
    const int c = blockIdx.y >> 2;
    const int jb = (blockIdx.y & 3) * 16;
    const float* src = W + (size_t)(c * 64 + jb) * N + n;
    __half* dst = Wc + ((size_t)c * N + n) * 64;
    const int p = n & 7;
    #pragma unroll
    for (int j = 0; j < 16; j += 8) {
        __half2 h0 = __floats2half2_rn(src[(size_t)(j + 0) * N], src[(size_t)(j + 1) * N]);
        __half2 h1 = __floats2half2_rn(src[(size_t)(j + 2) * N], src[(size_t)(j + 3) * N]);
        __half2 h2 = __floats2half2_rn(src[(size_t)(j + 4) * N], src[(size_t)(j + 5) * N]);
        __half2 h3 = __floats2half2_rn(src[(size_t)(j + 6) * N], src[(size_t)(j + 7) * N]);
        uint4 v = make_uint4(*(unsigned int*)&h0, *(unsigned int*)&h1,
                             *(unsigned int*)&h2, *(unsigned int*)&h3);
        *(uint4*)(dst + ((((j + jb) >> 3) ^ p) << 3)) = v;
    }
}

// LayerNorm + modulate -> fp16 A-layout output
__global__ void ln_mod(const float* __restrict__ x, __half* __restrict__ dst,
                       const float* __restrict__ shift, const float* __restrict__ scale,
                       int row0) {
    const int row = row0 + blockIdx.x;
    const int t = threadIdx.x;
    const float* xr = x + (size_t)blockIdx.x * HS;
    float v[12];
    float s = 0.0f;
    #pragma unroll
    for (int i = 0; i < 12; i++) { v[i] = xr[t + i * 256]; s += v[i]; }
    __shared__ float red[256];
    red[t] = s; __syncthreads();
    for (int o = 128; o > 0; o >>= 1) { if (t < o) red[t] += red[t + o]; __syncthreads(); }
    float mean = red[0] * (1.0f / HS);
    __syncthreads();
    float s2 = 0.0f;
    #pragma unroll
    for (int i = 0; i < 12; i++) { float d = v[i] - mean; s2 += d * d; }
    red[t] = s2; __syncthreads();
    for (int o = 128; o > 0; o >>= 1) { if (t < o) red[t] += red[t + o]; __syncthreads(); }
    float inv = rsqrtf(red[0] * (1.0f / HS) + 1e-6f);
    #pragma unroll
    for (int i = 0; i < 12; i++) {
        int c = t + i * 256;
        float val = shift[c] + (1.0f + scale[c]) * (v[i] - mean) * inv;
        dst[aoff16(row, c, LTOT)] = __float2half_rn(val);
    }
}

#define FA_SCALE 0.08838834764831845f

// RMS-norm + RoPE + head-major scatter; fp16 in/out, Q pre-scaled.
__global__ void rms_rope(const __half* __restrict__ qkv, const float* __restrict__ pe,
                         const float* __restrict__ tqs, const float* __restrict__ tks,
                         const float* __restrict__ iqs, const float* __restrict__ iks,
                         __half* __restrict__ Q, __half* __restrict__ Kp,
                         __half* __restrict__ Vp) {
    int l = blockIdx.x;
    int w = threadIdx.x >> 5, lane = threadIdx.x & 31;
    const float* qs = (l < LTXT) ? tqs : iqs;
    const float* ks = (l < LTXT) ? tks : iks;
    const __half* row = qkv + (size_t)l * QKVW;
    const float* peb = pe + (size_t)l * 256 + lane * 8;
    float4 p0 = *(const float4*)(peb);
    float4 p1 = *(const float4*)(peb + 4);
    int d0 = lane * 4;
    float4 scq = *(const float4*)(qs + d0);
    float4 sck = *(const float4*)(ks + d0);

    for (int h = w; h < NH; h += 8) {
        const __half2* qp = (const __half2*)(row + h * HD + d0);
        float2 xq0 = __half22float2(qp[0]);
        float2 xq1 = __half22float2(qp[1]);
        float ss = xq0.x*xq0.x + xq0.y*xq0.y + xq1.x*xq1.x + xq1.y*xq1.y;
        #pragma unroll
        for (int o = 16; o > 0; o >>= 1) ss += __shfl_xor_sync(0xffffffffu, ss, o);
        float r = rsqrtf(ss * (1.0f / HD) + 1e-6f);
        float x0 = xq0.x * r * scq.x, x1 = xq0.y * r * scq.y;
        float x2 = xq1.x * r * scq.z, x3 = xq1.y * r * scq.w;
        float q0 = (p0.x * x0 + p0.y * x1) * FA_SCALE;
        float q1 = (p0.z * x0 + p0.w * x1) * FA_SCALE;
        float q2 = (p1.x * x2 + p1.y * x3) * FA_SCALE;
        float q3 = (p1.z * x2 + p1.w * x3) * FA_SCALE;
        __half2 qa = __floats2half2_rn(q0, q1);
        __half2 qb = __floats2half2_rn(q2, q3);
        *(uint2*)(Q + ((size_t)h * LTOT + l) * HD + d0) =
            make_uint2(*(unsigned int*)&qa, *(unsigned int*)&qb);

        const __half2* kp2 = (const __half2*)(row + HS + h * HD + d0);
        float2 xk0 = __half22float2(kp2[0]);
        float2 xk1 = __half22float2(kp2[1]);
        float sk = xk0.x*xk0.x + xk0.y*xk0.y + xk1.x*xk1.x + xk1.y*xk1.y;
        #pragma unroll
        for (int o = 16; o > 0; o >>= 1) sk += __shfl_xor_sync(0xffffffffu, sk, o);
        float rk = rsqrtf(sk * (1.0f / HD) + 1e-6f);
        float y0 = xk0.x * rk * sck.x, y1 = xk0.y * rk * sck.y;
        float y2 = xk1.x * rk * sck.z, y3 = xk1.y * rk * sck.w;
        float k0 = p0.x * y0 + p0.y * y1;
        float k1 = p0.z * y0 + p0.w * y1;
        float k2 = p1.x * y2 + p1.y * y3;
        float k3 = p1.z * y2 + p1.w * y3;
        __half2 ka = __floats2half2_rn(k0, k1);
        __half2 kb = __floats2half2_rn(k2, k3);
        *(uint2*)(Kp + ((size_t)h * LTOT + l) * HD + d0) =
            make_uint2(*(unsigned int*)&ka, *(unsigned int*)&kb);

        *(uint2*)(Vp + ((size_t)h * LTOT + l) * HD + d0) =
            *(const uint2*)(row + 2 * HS + h * HD + d0);
    }
}

#define TCG_SMEM_BYTES (1024 + 4 * 32768)   // 2 stages of (32KB A + 32KB B)

#if HAS_TCGEN05
__device__ __forceinline__ uint32_t elect_one() {
    uint32_t pred;
    asm volatile("{\n\t.reg .pred p;\n\telect.sync _|p, 0xFFFFFFFF;\n\t"
                 "selp.b32 %0, 1, 0, p;\n\t}" : "=r"(pred));
    return pred;
}
__device__ __forceinline__ void mbar_wait(uint32_t mbar, uint32_t parity) {
    asm volatile(
        "{\n\t.reg .pred P1;\n\t"
        "W_%=:\n\t"
        "mbarrier.try_wait.parity.acquire.cta.shared::cta.b64 P1, [%0], %1, 0x989680;\n\t"
        "@P1 bra.uni D_%=;\n\t"
        "bra.uni W_%=;\n\t"
        "D_%=:\n\t}"
        :: "r"(mbar), "r"(parity) : "memory");
}
__device__ __forceinline__ uint64_t make_desc(uint32_t addr) {
    const uint64_t base =
        (uint64_t(2) << 61) | (uint64_t(1) << 46) | (uint64_t(64) << 32) | (uint64_t(1) << 16);
    return base | ((uint64_t)(addr >> 4) & 0x3FFF);
}
__device__ __forceinline__ void tc_mma_f16(uint32_t d, uint64_t ad, uint64_t bd,
                                           uint32_t idesc, uint32_t en) {
    asm volatile(
        "{\n\t.reg .pred p;\n\t"
        "setp.ne.u32 p, %4, 0;\n\t"
        "tcgen05.mma.cta_group::1.kind::f16 [%0], %1, %2, %3, {%5,%5,%5,%5}, p;\n\t}"
        :: "r"(d), "l"(ad), "l"(bd), "r"(idesc), "r"(en), "r"(0u) : "memory");
}
#define TCG_IDESC ((1u<<4)|((256u/8)<<17)|((128u/16)<<24))
#define EXPECT_TX(mbar, bytes) \
    asm volatile("mbarrier.arrive.expect_tx.shared.b64 _, [%0], %1;" \
                 :: "r"(mbar), "r"(bytes) : "memory")
#define BULK_CP(dst, src, bytes, mbar) \
    asm volatile("cp.async.bulk.shared::cluster.global.mbarrier::complete_tx::bytes " \
                 "[%0], [%1], %2, [%3];" \
                 :: "r"(dst), "l"(src), "r"(bytes), "r"(mbar) : "memory")
#endif

// ---------------------------------------------------------------------------
// Merged txt/img fp16 GEMM, CTA 256(M)x256(N): two 128-row MMAs share one B
// stage (halves B DMA traffic). TMEM = 512 cols (two accumulators).
// A: [K/64][lda rows][64] halves. B: [K/64][ldb cols][64] halves.
// EPI: 0 bias -> fp32 row-major; 1 gelu(bias) -> fp16 A-layout (rows=LTOT);
//      2 resid + gate*(bias) -> fp32 row-major; 3 bias -> fp16 row-major.
// ---------------------------------------------------------------------------
template <int EPI>
__global__ void __launch_bounds__(256)
tc_gemm(const __half* __restrict__ A,
        const __half* __restrict__ Bt, const __half* __restrict__ Bi,
        const float* __restrict__ biast, const float* __restrict__ biasi,
        float* __restrict__ Ct, float* __restrict__ Ci, __half* __restrict__ Ch,
        int K, int lda, int ldb, int ldc,
        const float* __restrict__ gatet, const float* __restrict__ gatei,
        const float* __restrict__ residt, const float* __restrict__ residi,
        int ldres) {
    extern __shared__ char smem[];
    const int t = threadIdx.x;
    const int wid = t >> 5, lane = t & 31;
    const int mi = blockIdx.x % NMALL;
    const int m0 = mi * 256;
    const int n0 = (blockIdx.x / NMALL) * 256;
    const bool is_txt = (mi < NMT);
    const __half* B    = is_txt ? Bt : Bi;
    const float* bias  = is_txt ? biast : biasi;
    const float* gate  = is_txt ? gatet : gatei;
    const float* resid = is_txt ? residt : residi;
    float* C           = is_txt ? Ct : Ci;
    const int nc = K / 64;

#if HAS_TCGEN05
    const uint32_t smem_base = smem_u32(smem);
    const uint32_t sA0 = (smem_base + 64 + 1023) & ~1023u;
    const uint32_t sB0 = sA0 + 32768;
    const uint32_t sA1 = sB0 + 32768;
    const uint32_t sB1 = sA1 + 32768;
    const uint32_t tx0 = smem_base + 16, tx1 = smem_base + 24;
    const uint32_t mm0 = smem_base + 32, mm1 = smem_base + 40;
    const uint32_t dn  = smem_base + 48;
    float* sEp = (float*)(smem + (sA0 - smem_base));   // 128*65*4 = 33.3KB, fits A0+B0

    if (wid == 0) {
        asm volatile("tcgen05.alloc.cta_group::1.sync.aligned.shared::cta.b32 [%0], %1;"
                     :: "r"(smem_base), "r"(512u) : "memory");
        asm volatile("tcgen05.relinquish_alloc_permit.cta_group::1.sync.aligned;");
    }
    if (t == 0) {
        asm volatile("mbarrier.init.shared.b64 [%0], 1;" :: "r"(tx0) : "memory");
        asm volatile("mbarrier.init.shared.b64 [%0], 1;" :: "r"(tx1) : "memory");
        asm volatile("mbarrier.init.shared.b64 [%0], 1;" :: "r"(mm0) : "memory");
        asm volatile("mbarrier.init.shared.b64 [%0], 1;" :: "r"(mm1) : "memory");
        asm volatile("mbarrier.init.shared.b64 [%0], 1;" :: "r"(dn)  : "memory");
    }
    __syncthreads();
    uint32_t tmem;
    asm volatile("ld.shared.b32 %0, [%1];" : "=r"(tmem) : "r"(smem_base));

    if (wid == 0 && elect_one()) {
        const __half* Ab = A + (size_t)m0 * 64;
        const __half* Bb = B + (size_t)n0 * 64;
        EXPECT_TX(tx0, 65536u);
        BULK_CP(sA0, Ab, 32768u, tx0);
        BULK_CP(sB0, Bb, 32768u, tx0);
        EXPECT_TX(tx1, 65536u);
        BULK_CP(sA1, Ab + (size_t)lda * 64, 32768u, tx1);
        BULK_CP(sB1, Bb + (size_t)ldb * 64, 32768u, tx1);
        asm volatile("tcgen05.fence::after_thread_sync;" ::: "memory");

        int phtx0 = 0, phtx1 = 0, phmm0 = 0, phmm1 = 0;
        for (int c = 0; c < nc; c++) {
            const int s = c & 1;
            if (s == 0) { mbar_wait(tx0, phtx0); phtx0 ^= 1; }
            else        { mbar_wait(tx1, phtx1); phtx1 ^= 1; }
            const uint32_t sAc = s ? sA1 : sA0;
            uint64_t bd = make_desc(s ? sB1 : sB0);
            #pragma unroll
            for (int mh = 0; mh < 2; mh++) {
                uint64_t ad = make_desc(sAc + mh * 16384);
                #pragma unroll
                for (int ks = 0; ks < 4; ks++)
                    tc_mma_f16(tmem + mh * 256, ad + 2 * ks, bd + 2 * ks, TCG_IDESC,
                               (uint32_t)((c > 0) | (ks > 0)));
            }
            asm volatile(
                "tcgen05.commit.cta_group::1.mbarrier::arrive::one.shared::cluster.b64 [%0];"
                :: "r"(s ? mm1 : mm0) : "memory");
            if (c == nc - 1) {
                asm volatile(
                    "tcgen05.commit.cta_group::1.mbarrier::arrive::one.shared::cluster.b64 [%0];"
                    :: "r"(dn) : "memory");
            }
            if (c + 2 < nc) {
                if (s == 0) { mbar_wait(mm0, phmm0); phmm0 ^= 1; }
                else        { mbar_wait(mm1, phmm1); phmm1 ^= 1; }
                const uint32_t txm = s ? tx1 : tx0;
                EXPECT_TX(txm, 65536u);
                BULK_CP(s ? sA1 : sA0, Ab + (size_t)(c + 2) * lda * 64, 32768u, txm);
                BULK_CP(s ? sB1 : sB0, Bb + (size_t)(c + 2) * ldb * 64, 32768u, txm);
            }
        }
    }
    mbar_wait(dn, 0);
    asm volatile("tcgen05.fence::after_thread_sync;" ::: "memory");
    __syncthreads();

    // ---- epilogue: per m-half, TMEM -> smem bounce -> coalesced stores ----
    const int half = wid >> 2;
    const int rrow = (wid & 3) * 32 + lane;
    const int f = t & 15, rg = t >> 4;
    for (int mh = 0; mh < 2; mh++) {
        const uint32_t tm = tmem + mh * 256;
        const int m0h = m0 + mh * 128;
        for (int cb = 0; cb < 4; cb++) {
            uint32_t r_[32];
            asm volatile(
                "tcgen05.ld.sync.aligned.32x32b.x32.b32 "
                "{%0,%1,%2,%3,%4,%5,%6,%7,%8,%9,%10,%11,%12,%13,%14,%15,"
                "%16,%17,%18,%19,%20,%21,%22,%23,%24,%25,%26,%27,%28,%29,%30,%31}, [%32];"
                : "=r"(r_[0]),"=r"(r_[1]),"=r"(r_[2]),"=r"(r_[3]),
                  "=r"(r_[4]),"=r"(r_[5]),"=r"(r_[6]),"=r"(r_[7]),
                  "=r"(r_[8]),"=r"(r_[9]),"=r"(r_[10]),"=r"(r_[11]),
                  "=r"(r_[12]),"=r"(r_[13]),"=r"(r_[14]),"=r"(r_[15]),
                  "=r"(r_[16]),"=r"(r_[17]),"=r"(r_[18]),"=r"(r_[19]),
                  "=r"(r_[20]),"=r"(r_[21]),"=r"(r_[22]),"=r"(r_[23]),
                  "=r"(r_[24]),"=r"(r_[25]),"=r"(r_[26]),"=r"(r_[27]),
                  "=r"(r_[28]),"=r"(r_[29]),"=r"(r_[30]),"=r"(r_[31])
                : "r"(tm + half * 128 + cb * 32));
            asm volatile("tcgen05.wait::ld.sync.aligned;" ::: "memory");
            #pragma unroll
            for (int j = 0; j < 32; j++)
                sEp[rrow * 65 + half * 32 + j] = __uint_as_float(r_[j]);
            __syncthreads();

            const int scol = (f >> 3) * 32 + (f & 7) * 4;
            const int gcol = n0 + (f >> 3) * 128 + cb * 32 + (f & 7) * 4;
            const float4 bv = *(const float4*)(bias + gcol);
            float4 gv = make_float4(0.f, 0.f, 0.f, 0.f);
            if (EPI == 2) gv = *(const float4*)(gate + gcol);
            #pragma unroll
            for (int i = 0; i < 8; i++) {
                int r = rg + 16 * i;
                int m = m0h + r;
                const float* sp = &sEp[r * 65 + scol];
                float4 v = make_float4(sp[0], sp[1], sp[2], sp[3]);
                v.x += bv.x; v.y += bv.y; v.z += bv.z; v.w += bv.w;
                if (EPI == 1) {
                    v.x = gelu_tanh(v.x); v.y = gelu_tanh(v.y);
                    v.z = gelu_tanh(v.z); v.w = gelu_tanh(v.w);
                    size_t ad2 = ((size_t)(gcol >> 6) * LTOT + m) * 64 +
                                 (((((gcol >> 3) & 7) ^ (m & 7)) << 3) + (gcol & 7));
                    __half2 ha = __floats2half2_rn(v.x, v.y);
                    __half2 hb = __floats2half2_rn(v.z, v.w);
                    *(uint2*)(Ch + ad2) = make_uint2(*(unsigned int*)&ha, *(unsigned int*)&hb);
                } else if (EPI == 3) {
                    __half2 ha = __floats2half2_rn(v.x, v.y);
                    __half2 hb = __floats2half2_rn(v.z, v.w);
                    *(uint2*)(Ch + (size_t)m * ldc + gcol) =
                        make_uint2(*(unsigned int*)&ha, *(unsigned int*)&hb);
                } else {
                    if (EPI == 2) {
                        float4 rr = *(const float4*)(resid + (size_t)m * ldres + gcol);
                        v.x = rr.x + gv.x * v.x; v.y = rr.y + gv.y * v.y;
                        v.z = rr.z + gv.z * v.z; v.w = rr.w + gv.w * v.w;
                    }
                    *(float4*)(C + (size_t)m * ldc + gcol) = v;
                }
            }
            __syncthreads();
        }
    }
    if (wid == 0) {
        asm volatile("tcgen05.dealloc.cta_group::1.sync.aligned.b32 %0, %1;"
                     :: "r"(tmem), "r"(512u));
    }
#else
    for (int e = t; e < 256 * 256; e += 256) {
        int r = e >> 8, j = e & 255;
        int m = m0 + r, n = n0 + j;
        float acc = 0.f;
        for (int k = 0; k < K; k++) {
            float a = __half2float(A[aoff16(m, k, lda)]);
            float b = __half2float(B[aoff16(n, k, ldb)]);
            acc += a * b;
        }
        acc += bias[n];
        if (EPI == 1) {
            acc = gelu_tanh(acc);
            Ch[aoff16(m, n, LTOT)] = __float2half_rn(acc);
        } else if (EPI == 3) {
            Ch[(size_t)m * ldc + n] = __float2half_rn(acc);
        } else {
            if (EPI == 2) acc = resid[(size_t)m * ldres + n] + gate[n] * acc;
            C[(size_t)m * ldc + n] = acc;
        }
    }
#endif
}

// ---------------------------------------------------------------------------
// fp16 flash attention (unchanged from R13, known good)
// ---------------------------------------------------------------------------
#define KPITCH 136
#define PPITCH 72
#define SK_OFF 0
#define SV_OFF (64 * KPITCH)
#define SP_OFF (2 * 64 * KPITCH)
#define FA_SMEM_BYTES ((2 * 64 * KPITCH + 8 * 16 * PPITCH) * 2)

__global__ void __launch_bounds__(256, 1)
flash_attn(const __half* __restrict__ Q, const __half* __restrict__ K,
           const __half* __restrict__ V, __half* __restrict__ O) {
    extern __shared__ __half smh[];
    __half* sK = smh + SK_OFF;
    __half* sV = smh + SV_OFF;
    __half* sP = smh + SP_OFF;

    const int t = threadIdx.x;
    const int wid = t >> 5, lane = t & 31;
    const int gid = lane >> 2, tig = lane & 3;
    const int h = blockIdx.y;
    const int q0 = blockIdx.x * 128;
    const int m0 = wid * 16;
    __half* sPw = sP + wid * 16 * PPITCH;

    const __half* Qh = Q + ((size_t)h * LTOT + q0) * HD;
    const __half* Kh = K + (size_t)h * LTOT * HD;
    const __half* Vh = V + (size_t)h * LTOT * HD;

    unsigned int qf[8][4];
    #pragma unroll
    for (int kb = 0; kb < 8; kb++) {
        const __half* qr = Qh + (size_t)(m0 + gid) * HD + kb * 16 + 2 * tig;
        qf[kb][0] = *(const unsigned int*)(qr);
        qf[kb][1] = *(const unsigned int*)(qr + 8 * HD);
        qf[kb][2] = *(const unsigned int*)(qr + 8);
        qf[kb][3] = *(const unsigned int*)(qr + 8 * HD + 8);
    }

    float co[16][4];
    #pragma unroll
    for (int i = 0; i < 16; i++)
        #pragma unroll
        for (int j = 0; j < 4; j++) co[i][j] = 0.0f;
    float mrow0 = -1e30f, mrow1 = -1e30f, lrow0 = 0.0f, lrow1 = 0.0f;

    for (int kv = 0; kv < LTOT; kv += 64) {
        __syncthreads();
        {
            const int c = t >> 2;
            const int dseg = (t & 3) * 32;
            const __half* kr = Kh + (size_t)(kv + c) * HD + dseg;
            const __half* vr = Vh + (size_t)(kv + c) * HD + dseg;
            #pragma unroll
            for (int i = 0; i < 4; i++)
                *(uint4*)(sK + c * KPITCH + dseg + i * 8) = *(const uint4*)(kr + i * 8);
            #pragma unroll
            for (int i = 0; i < 4; i++)
                *(uint4*)(sV + c * KPITCH + dseg + i * 8) = *(const uint4*)(vr + i * 8);
        }
        __syncthreads();

        float cs[8][4];
        #pragma unroll
        for (int i = 0; i < 8; i++)
            #pragma unroll
            for (int j = 0; j < 4; j++) cs[i][j] = 0.0f;
        #pragma unroll
        for (int kb = 0; kb < 8; kb++) {
            #pragma unroll
            for (int nt = 0; nt < 8; nt++) {
                const __half* kp = sK + (nt * 8 + gid) * KPITCH + kb * 16 + 2 * tig;
                unsigned int b0 = *(const unsigned int*)(kp);
                unsigned int b1 = *(const unsigned int*)(kp + 8);
                mma_f16(cs[nt], qf[kb], b0, b1);
            }
        }

        float rmax0 = -1e30f, rmax1 = -1e30f;
        #pragma unroll
        for (int nt = 0; nt < 8; nt++) {
            rmax0 = fmaxf(rmax0, fmaxf(cs[nt][0], cs[nt][1]));
            rmax1 = fmaxf(rmax1, fmaxf(cs[nt][2], cs[nt][3]));
        }
        rmax0 = fmaxf(rmax0, __shfl_xor_sync(0xffffffffu, rmax0, 1));
        rmax0 = fmaxf(rmax0, __shfl_xor_sync(0xffffffffu, rmax0, 2));
        rmax1 = fmaxf(rmax1, __shfl_xor_sync(0xffffffffu, rmax1, 1));
        rmax1 = fmaxf(rmax1, __shfl_xor_sync(0xffffffffu, rmax1, 2));
        float mn0 = fmaxf(mrow0, rmax0);
        float mn1 = fmaxf(mrow1, rmax1);
        float corr0 = __expf(mrow0 - mn0);
        float corr1 = __expf(mrow1 - mn1);
        mrow0 = mn0; mrow1 = mn1;

        float rs0 = 0.0f, rs1 = 0.0f;
        #pragma unroll
        for (int nt = 0; nt < 8; nt++) {
            cs[nt][0] = __expf(cs[nt][0] - mn0);
            cs[nt][1] = __expf(cs[nt][1] - mn0);
            cs[nt][2] = __expf(cs[nt][2] - mn1);
            cs[nt][3] = __expf(cs[nt][3] - mn1);
            rs0 += cs[nt][0] + cs[nt][1];
            rs1 += cs[nt][2] + cs[nt][3];
        }
        rs0 += __shfl_xor_sync(0xffffffffu, rs0, 1);
        rs0 += __shfl_xor_sync(0xffffffffu, rs0, 2);
        rs1 += __shfl_xor_sync(0xffffffffu, rs1, 1);
        rs1 += __shfl_xor_sync(0xffffffffu, rs1, 2);
        lrow0 = lrow0 * corr0 + rs0;
        lrow1 = lrow1 * corr1 + rs1;

        #pragma unroll
        for (int nt = 0; nt < 16; nt++) {
            co[nt][0] *= corr0; co[nt][1] *= corr0;
            co[nt][2] *= corr1; co[nt][3] *= corr1;
        }

        #pragma unroll
        for (int nt = 0; nt < 8; nt++) {
            __half2 p01 = __floats2half2_rn(cs[nt][0], cs[nt][1]);
            __half2 p23 = __floats2half2_rn(cs[nt][2], cs[nt][3]);
            *(unsigned int*)(sPw + gid * PPITCH + nt * 8 + 2 * tig) = *(unsigned int*)&p01;
            *(unsigned int*)(sPw + (gid + 8) * PPITCH + nt * 8 + 2 * tig) = *(unsigned int*)&p23;
        }
        __syncwarp();

        unsigned int pf[4][4];
        #pragma unroll
        for (int kb = 0; kb < 4; kb++) {
            const __half* pp = sPw + gid * PPITCH + kb * 16 + 2 * tig;
            pf[kb][0] = *(const unsigned int*)(pp);
            pf[kb][1] = *(const unsigned int*)(pp + 8 * PPITCH);
            pf[kb][2] = *(const unsigned int*)(pp + 8);
            pf[kb][3] = *(const unsigned int*)(pp + 8 * PPITCH + 8);
        }

        #pragma unroll
        for (int nt = 0; nt < 16; nt++) {
            #pragma unroll
            for (int cb = 0; cb < 2; cb++) {
                uint32_t va = smem_u32(sV + (cb * 32 + lane) * KPITCH + nt * 8);
                unsigned int v0, v1, v2, v3;
                asm volatile(
                    "ldmatrix.sync.aligned.m8n8.x4.trans.shared.b16 {%0,%1,%2,%3}, [%4];"
                    : "=r"(v0), "=r"(v1), "=r"(v2), "=r"(v3) : "r"(va));
                mma_f16(co[nt], pf[cb * 2 + 0], v0, v1);
                mma_f16(co[nt], pf[cb * 2 + 1], v2, v3);
            }
        }
    }

    float inv0 = 1.0f / lrow0;
    float inv1 = 1.0f / lrow1;
    int ra = q0 + m0 + gid;
    int rb = ra + 8;
    #pragma unroll
    for (int nt = 0; nt < 16; nt++) {
        int col = h * HD + nt * 8 + tig * 2;
        int q = (col >> 3) & 7, e = col & 7;
        size_t base = (size_t)(col >> 6) * LTOT * 64;
        __half2 va = __floats2half2_rn(co[nt][0] * inv0, co[nt][1] * inv0);
        __half2 vb = __floats2half2_rn(co[nt][2] * inv1, co[nt][3] * inv1);
        *(unsigned int*)(O + base + (size_t)ra * 64 + ((q ^ (ra & 7)) << 3) + e) =
            *(unsigned int*)&va;
        *(unsigned int*)(O + base + (size_t)rb * 64 + ((q ^ (rb & 7)) << 3) + e) =
            *(unsigned int*)&vb;
    }
}

// ---------------------------------------------------------------------------
// Host launcher
// ---------------------------------------------------------------------------
static void tc_launch(int epi, const __half* A,
                      const __half* Bt, const __half* Bi,
                      const float* biast, const float* biasi,
                      float* Ct, float* Ci, __half* Ch,
                      int N, int K, int lda, int ldb, int ldc,
                      const float* gatet = nullptr, const float* gatei = nullptr,
                      const float* residt = nullptr, const float* residi = nullptr,
                      int ldres = 0) {
    dim3 grid(NMALL * (N / 256));
    if (epi == 0)
        tc_gemm<0><<<grid, 256, TCG_SMEM_BYTES>>>(A, Bt, Bi, biast, biasi, Ct, Ci, Ch,
                                                  K, lda, ldb, ldc, gatet, gatei, residt, residi, ldres);
    else if (epi == 1)
        tc_gemm<1><<<grid, 256, TCG_SMEM_BYTES>>>(A, Bt, Bi, biast, biasi, Ct, Ci, Ch,
                                                  K, lda, ldb, ldc, gatet, gatei, residt, residi, ldres);
    else if (epi == 2)
        tc_gemm<2><<<grid, 256, TCG_SMEM_BYTES>>>(A, Bt, Bi, biast, biasi, Ct, Ci, Ch,
                                                  K, lda, ldb, ldc, gatet, gatei, residt, residi, ldres);
    else
        tc_gemm<3><<<grid, 256, TCG_SMEM_BYTES>>>(A, Bt, Bi, biast, biasi, Ct, Ci, Ch,
                                                  K, lda, ldb, ldc, gatet, gatei, residt, residi, ldres);
}

extern "C" void kernel_launch(void* const* d_in, const int* in_sizes, int n_in,
                              void* d_out, int out_size) {
    const float* img        = (const float*)d_in[0];
    const float* txt        = (const float*)d_in[1];
    const float* vec        = (const float*)d_in[2];
    const float* pe         = (const float*)d_in[3];
    const float* img_mod_w  = (const float*)d_in[4];
    const float* img_mod_b  = (const float*)d_in[5];
    const float* img_qkv_w  = (const float*)d_in[6];
    const float* img_qkv_b  = (const float*)d_in[7];
    const float* img_q_s    = (const float*)d_in[8];
    const float* img_k_s    = (const float*)d_in[9];
    const float* img_proj_w = (const float*)d_in[10];
    const float* img_proj_b = (const float*)d_in[11];
    const float* img_mlp_w1 = (const float*)d_in[12];
    const float* img_mlp_b1 = (const float*)d_in[13];
    const float* img_mlp_w2 = (const float*)d_in[14];
    const float* img_mlp_b2 = (const float*)d_in[15];
    const float* txt_mod_w  = (const float*)d_in[16];
    const float* txt_mod_b  = (const float*)d_in[17];
    const float* txt_qkv_w  = (const float*)d_in[18];
    const float* txt_qkv_b  = (const float*)d_in[19];
    const float* txt_q_s    = (const float*)d_in[20];
    const float* txt_k_s    = (const float*)d_in[21];
    const float* txt_proj_w = (const float*)d_in[22];
    const float* txt_proj_b = (const float*)d_in[23];
    const float* txt_mlp_w1 = (const float*)d_in[24];
    const float* txt_mlp_b1 = (const float*)d_in[25];
    const float* txt_mlp_w2 = (const float*)d_in[26];
    const float* txt_mlp_b2 = (const float*)d_in[27];
    float* out = (float*)d_out;

    float *sv, *modi, *modt, *x1;
    __half *x, *attn, *x2, *h1, *w, *q, *k, *v, *qkvb;
    cudaGetSymbolAddress((void**)&sv,   g_silu);
    cudaGetSymbolAddress((void**)&modi, g_mod_img);
    cudaGetSymbolAddress((void**)&modt, g_mod_txt);
    cudaGetSymbolAddress((void**)&x,    g_x);
    cudaGetSymbolAddress((void**)&qkvb, g_qkv);
    cudaGetSymbolAddress((void**)&q,    g_q);
    cudaGetSymbolAddress((void**)&k,    g_k);
    cudaGetSymbolAddress((void**)&v,    g_v);
    cudaGetSymbolAddress((void**)&attn, g_attn);
    cudaGetSymbolAddress((void**)&x1,   g_x1);
    cudaGetSymbolAddress((void**)&x2,   g_x2);
    cudaGetSymbolAddress((void**)&h1,   g_h1);
    cudaGetSymbolAddress((void**)&w,    g_w);

    cudaFuncSetAttribute(flash_attn, cudaFuncAttributeMaxDynamicSharedMemorySize, FA_SMEM_BYTES);
    cudaFuncSetAttribute(tc_gemm<0>, cudaFuncAttributeMaxDynamicSharedMemorySize, TCG_SMEM_BYTES);
    cudaFuncSetAttribute(tc_gemm<1>, cudaFuncAttributeMaxDynamicSharedMemorySize, TCG_SMEM_BYTES);
    cudaFuncSetAttribute(tc_gemm<2>, cudaFuncAttributeMaxDynamicSharedMemorySize, TCG_SMEM_BYTES);
    cudaFuncSetAttribute(tc_gemm<3>, cudaFuncAttributeMaxDynamicSharedMemorySize, TCG_SMEM_BYTES);

    // weight conversion (chunk-major fp16, pre-swizzled), 4 blocks per chunk
    conv_w<<<dim3(QKVW / 256, HS / 16),   256>>>(txt_qkv_w,  w + OFF_QKV_T,  QKVW);
    conv_w<<<dim3(QKVW / 256, HS / 16),   256>>>(img_qkv_w,  w + OFF_QKV_I,  QKVW);
    conv_w<<<dim3(HS / 256,   HS / 16),   256>>>(txt_proj_w, w + OFF_PROJ_T, HS);
    conv_w<<<dim3(HS / 256,   HS / 16),   256>>>(img_proj_w, w + OFF_PROJ_I, HS);
    conv_w<<<dim3(MLPD / 256, HS / 16),   256>>>(txt_mlp_w1, w + OFF_MLP1_T, MLPD);
    conv_w<<<dim3(MLPD / 256, HS / 16),   256>>>(img_mlp_w1, w + OFF_MLP1_I, MLPD);
    conv_w<<<dim3(HS / 256,   MLPD / 16), 256>>>(txt_mlp_w2, w + OFF_MLP2_T, HS);
    conv_w<<<dim3(HS / 256,   MLPD / 16), 256>>>(img_mlp_w2, w + OFF_MLP2_I, HS);

    silu_kernel<<<HS / 256, 256>>>(vec, sv);
    mod_gemv2<<<(6 * HS) / 64, 256>>>(sv, img_mod_w, img_mod_b, modi);
    mod_gemv2<<<(6 * HS) / 64, 256>>>(sv, txt_mod_w, txt_mod_b, modt);

    ln_mod<<<LTXT, 256>>>(txt, x, modt + 0 * HS, modt + 1 * HS, 0);
    ln_mod<<<LIMG, 256>>>(img, x, modi + 0 * HS, modi + 1 * HS, LTXT);

    // QKV (merged txt/img) -> fp16 row-major qkvb
    tc_launch(3, x, w + OFF_QKV_T, w + OFF_QKV_I, txt_qkv_b, img_qkv_b,
              nullptr, nullptr, qkvb, QKVW, HS, LTOT, QKVW, QKVW);

    rms_rope<<<LTOT, 256>>>(qkvb, pe, txt_q_s, txt_k_s, img_q_s, img_k_s, q, k, v);

    {
        dim3 fgrid(LTOT / 128, NH);
        flash_attn<<<fgrid, 256, FA_SMEM_BYTES>>>(q, k, v, attn);
    }

    // proj + gated residual (merged) -> row-major fp32 x1
    tc_launch(2, attn, w + OFF_PROJ_T, w + OFF_PROJ_I, txt_proj_b, img_proj_b,
              x1, x1, nullptr, HS, HS, LTOT, HS, HS,
              modt + 2 * HS, modi + 2 * HS,
              txt, img - (size_t)LTXT * HS, HS);

    ln_mod<<<LTXT, 256>>>(x1, x2,                     modt + 3 * HS, modt + 4 * HS, 0);
    ln_mod<<<LIMG, 256>>>(x1 + (size_t)LTXT * HS, x2, modi + 3 * HS, modi + 4 * HS, LTXT);

    // MLP1 (+GELU, merged) -> fp16 A-layout h1
    tc_launch(1, x2, w + OFF_MLP1_T, w + OFF_MLP1_I, txt_mlp_b1, img_mlp_b1,
              nullptr, nullptr, h1, MLPD, HS, LTOT, MLPD, MLPD);

    // MLP2 (+gated residual, merged) -> d_out (img first, then txt)
    tc_launch(2, h1, w + OFF_MLP2_T, w + OFF_MLP2_I, txt_mlp_b2, img_mlp_b2,
              out + (size_t)LIMG * HS,
              out - (size_t)LTXT * HS,
              nullptr, HS, MLPD, LTOT, HS, HS,
              modt + 5 * HS, modi + 5 * HS,
              x1, x1, HS);
}

// round 15
// speedup vs baseline: 1.0872x; 1.0872x over previous
#include <cuda_runtime.h>
#include <cuda_bf16.h>
#include <cuda_fp16.h>
#include <math.h>
#include <stdint.h>

#define HS    3072
#define MLPD  12288
#define NH    24
#define HD    128
#define LTXT  512
#define LIMG  2048
#define LTOT  2560
#define QKVW  9216
#define NMT   4      // txt M-tiles (512/128)
#define NMALL 20     // total M-tiles (2560/128)

#if defined(__CUDA_ARCH__)
#if defined(__CUDA_ARCH_FEAT_SM103_ALL) || \
    (defined(__CUDA_ARCH_SPECIFIC__) && (__CUDA_ARCH_SPECIFIC__ >= 1000))
#define HAS_TCGEN05 1
#else
#define HAS_TCGEN05 0
#endif
#else
#define HAS_TCGEN05 0
#endif

// ---------------------------------------------------------------------------
// Static device scratch
// ---------------------------------------------------------------------------
__device__ float g_silu[HS];
__device__ float g_mod_img[6 * HS];
__device__ float g_mod_txt[6 * HS];
// A-operand buffers: chunk-major fp16 layout [K/64][LTOT][64], pre-swizzled
__device__ __align__(1024) __half g_x   [(size_t)LTOT * HS];
__device__ __align__(1024) __half g_attn[(size_t)LTOT * HS];
__device__ __align__(1024) __half g_x2  [(size_t)LTOT * HS];
__device__ __align__(1024) __half g_h1  [(size_t)LTOT * MLPD];
// row-major buffers
__device__ __half g_qkv [(size_t)LTOT * QKVW];
__device__ __half g_q   [(size_t)NH * LTOT * HD];   // pre-scaled by FA_SCALE
__device__ __half g_k   [(size_t)NH * LTOT * HD];
__device__ __half g_v   [(size_t)NH * LTOT * HD];
__device__ float  g_x1  [(size_t)LTOT * HS];
// converted weights: chunk-major fp16, pre-swizzled [K/64][N][64]
#define OFF_QKV_T  0u
#define OFF_QKV_I  28311552u
#define OFF_PROJ_T 56623104u
#define OFF_PROJ_I 66060288u
#define OFF_MLP1_T 75497472u
#define OFF_MLP1_I 113246208u
#define OFF_MLP2_T 150994944u
#define OFF_MLP2_I 188743680u
__device__ __align__(1024) __half g_w[226492416];

// ---------------------------------------------------------------------------
// Helpers
// ---------------------------------------------------------------------------
__device__ __forceinline__ float gelu_tanh(float x) {
    float x3 = x * x * x;
    return 0.5f * x * (1.0f + tanhf(0.7978845608028654f * (x + 0.044715f * x3)));
}
__device__ __forceinline__ uint32_t smem_u32(const void* p) {
    uint32_t a;
    asm("{ .reg .u64 t; cvta.to.shared.u64 t, %1; cvt.u32.u64 %0, t; }" : "=r"(a) : "l"(p));
    return a;
}
__device__ __forceinline__ size_t aoff16(int row, int k, int rows) {
    int q = (k >> 3) & 7;
    return ((size_t)(k >> 6) * rows + row) * 64 + (((q ^ (row & 7)) << 3) + (k & 7));
}
__device__ __forceinline__ void mma_f16(float c[4], const unsigned int a[4],
                                        unsigned int b0, unsigned int b1) {
    asm volatile(
        "mma.sync.aligned.m16n8k16.row.col.f32.f16.f16.f32 "
        "{%0,%1,%2,%3}, {%4,%5,%6,%7}, {%8,%9}, {%0,%1,%2,%3};"
        : "+f"(c[0]), "+f"(c[1]), "+f"(c[2]), "+f"(c[3])
        : "r"(a[0]), "r"(a[1]), "r"(a[2]), "r"(a[3]), "r"(b0), "r"(b1));
}

// ---------------------------------------------------------------------------
// Elementwise kernels
// ---------------------------------------------------------------------------
__global__ void silu_kernel(const float* __restrict__ v, float* __restrict__ o) {
    int i = blockIdx.x * 256 + threadIdx.x;
    if (i < HS) { float x = v[i]; o[i] = x / (1.0f + expf(-x)); }
}

__global__ void mod_gemv2(const float* __restrict__ sv, const float* __restrict__ w,
                          const float* __restrict__ b, float* __restrict__ out) {
    __shared__ float ssv[HS];
    __shared__ float red[4][64];
    for (int i = threadIdx.x; i < HS; i += 256) ssv[i] = sv[i];
    __syncthreads();
    const int jl = threadIdx.x & 63, kq = threadIdx.x >> 6;
    const int j = blockIdx.x * 64 + jl;
    const int i0 = kq * (HS / 4);
    float acc = 0.0f;
    #pragma unroll 8
    for (int i = 0; i < HS / 4; i++)
        acc += ssv[i0 + i] * w[(size_t)(i0 + i) * (6 * HS) + j];
    red[kq][jl] = acc;
    __syncthreads();
    if (threadIdx.x < 64) {
        int jj = blockIdx.x * 64 + threadIdx.x;
        out[jj] = red[0][threadIdx.x] + red[1][threadIdx.x] +
                  red[2][threadIdx.x] + red[3][threadIdx.x] + b[jj];
    }
}

// weight conversion: W [K,N] row-major fp32 -> chunk-major fp16 pre-swizzled.
// Grid (N/256, K/16): each block covers a quarter of a 64-k chunk.
__global__ void conv_w(const float* __restrict__ W, __half* __restrict__ Wc, int N) {
    const int n = blockIdx.x * 256 + threadIdx.x;
    const int c = blockIdx.y >> 2;
    const int jb = (blockIdx.y & 3) * 16;
    const float* src = W + (size_t)(c * 64 + jb) * N + n;
    __half* dst = Wc + ((size_t)c * N + n) * 64;
    const int p = n & 7;
    #pragma unroll
    for (int j = 0; j < 16; j += 8) {
        __half2 h0 = __floats2half2_rn(src[(size_t)(j + 0) * N], src[(size_t)(j + 1) * N]);
        __half2 h1 = __floats2half2_rn(src[(size_t)(j + 2) * N], src[(size_t)(j + 3) * N]);
        __half2 h2 = __floats2half2_rn(src[(size_t)(j + 4) * N], src[(size_t)(j + 5) * N]);
        __half2 h3 = __floats2half2_rn(src[(size_t)(j + 6) * N], src[(size_t)(j + 7) * N]);
        uint4 v = make_uint4(*(unsigned int*)&h0, *(unsigned int*)&h1,
                             *(unsigned int*)&h2, *(unsigned int*)&h3);
        *(uint4*)(dst + ((((j + jb) >> 3) ^ p) << 3)) = v;
    }
}

// LayerNorm + modulate -> fp16 A-layout output
__global__ void ln_mod(const float* __restrict__ x, __half* __restrict__ dst,
                       const float* __restrict__ shift, const float* __restrict__ scale,
                       int row0) {
    const int row = row0 + blockIdx.x;
    const int t = threadIdx.x;
    const float* xr = x + (size_t)blockIdx.x * HS;
    float v[12];
    float s = 0.0f;
    #pragma unroll
    for (int i = 0; i < 12; i++) { v[i] = xr[t + i * 256]; s += v[i]; }
    __shared__ float red[256];
    red[t] = s; __syncthreads();
    for (int o = 128; o > 0; o >>= 1) { if (t < o) red[t] += red[t + o]; __syncthreads(); }
    float mean = red[0] * (1.0f / HS);
    __syncthreads();
    float s2 = 0.0f;
    #pragma unroll
    for (int i = 0; i < 12; i++) { float d = v[i] - mean; s2 += d * d; }
    red[t] = s2; __syncthreads();
    for (int o = 128; o > 0; o >>= 1) { if (t < o) red[t] += red[t + o]; __syncthreads(); }
    float inv = rsqrtf(red[0] * (1.0f / HS) + 1e-6f);
    #pragma unroll
    for (int i = 0; i < 12; i++) {
        int c = t + i * 256;
        float val = shift[c] + (1.0f + scale[c]) * (v[i] - mean) * inv;
        dst[aoff16(row, c, LTOT)] = __float2half_rn(val);
    }
}

#define FA_SCALE 0.08838834764831845f

// RMS-norm + RoPE + head-major scatter; fp16 in/out, Q pre-scaled.
__global__ void rms_rope(const __half* __restrict__ qkv, const float* __restrict__ pe,
                         const float* __restrict__ tqs, const float* __restrict__ tks,
                         const float* __restrict__ iqs, const float* __restrict__ iks,
                         __half* __restrict__ Q, __half* __restrict__ Kp,
                         __half* __restrict__ Vp) {
    int l = blockIdx.x;
    int w = threadIdx.x >> 5, lane = threadIdx.x & 31;
    const float* qs = (l < LTXT) ? tqs : iqs;
    const float* ks = (l < LTXT) ? tks : iks;
    const __half* row = qkv + (size_t)l * QKVW;
    const float* peb = pe + (size_t)l * 256 + lane * 8;
    float4 p0 = *(const float4*)(peb);
    float4 p1 = *(const float4*)(peb + 4);
    int d0 = lane * 4;
    float4 scq = *(const float4*)(qs + d0);
    float4 sck = *(const float4*)(ks + d0);

    for (int h = w; h < NH; h += 8) {
        const __half2* qp = (const __half2*)(row + h * HD + d0);
        float2 xq0 = __half22float2(qp[0]);
        float2 xq1 = __half22float2(qp[1]);
        float ss = xq0.x*xq0.x + xq0.y*xq0.y + xq1.x*xq1.x + xq1.y*xq1.y;
        #pragma unroll
        for (int o = 16; o > 0; o >>= 1) ss += __shfl_xor_sync(0xffffffffu, ss, o);
        float r = rsqrtf(ss * (1.0f / HD) + 1e-6f);
        float x0 = xq0.x * r * scq.x, x1 = xq0.y * r * scq.y;
        float x2 = xq1.x * r * scq.z, x3 = xq1.y * r * scq.w;
        float q0 = (p0.x * x0 + p0.y * x1) * FA_SCALE;
        float q1 = (p0.z * x0 + p0.w * x1) * FA_SCALE;
        float q2 = (p1.x * x2 + p1.y * x3) * FA_SCALE;
        float q3 = (p1.z * x2 + p1.w * x3) * FA_SCALE;
        __half2 qa = __floats2half2_rn(q0, q1);
        __half2 qb = __floats2half2_rn(q2, q3);
        *(uint2*)(Q + ((size_t)h * LTOT + l) * HD + d0) =
            make_uint2(*(unsigned int*)&qa, *(unsigned int*)&qb);

        const __half2* kp2 = (const __half2*)(row + HS + h * HD + d0);
        float2 xk0 = __half22float2(kp2[0]);
        float2 xk1 = __half22float2(kp2[1]);
        float sk = xk0.x*xk0.x + xk0.y*xk0.y + xk1.x*xk1.x + xk1.y*xk1.y;
        #pragma unroll
        for (int o = 16; o > 0; o >>= 1) sk += __shfl_xor_sync(0xffffffffu, sk, o);
        float rk = rsqrtf(sk * (1.0f / HD) + 1e-6f);
        float y0 = xk0.x * rk * sck.x, y1 = xk0.y * rk * sck.y;
        float y2 = xk1.x * rk * sck.z, y3 = xk1.y * rk * sck.w;
        float k0 = p0.x * y0 + p0.y * y1;
        float k1 = p0.z * y0 + p0.w * y1;
        float k2 = p1.x * y2 + p1.y * y3;
        float k3 = p1.z * y2 + p1.w * y3;
        __half2 ka = __floats2half2_rn(k0, k1);
        __half2 kb = __floats2half2_rn(k2, k3);
        *(uint2*)(Kp + ((size_t)h * LTOT + l) * HD + d0) =
            make_uint2(*(unsigned int*)&ka, *(unsigned int*)&kb);

        *(uint2*)(Vp + ((size_t)h * LTOT + l) * HD + d0) =
            *(const uint2*)(row + 2 * HS + h * HD + d0);
    }
}

#define TCG_SMEM_BYTES (1024 + 2 * 49152)   // 2 stages of (16KB A + 32KB B)

#if HAS_TCGEN05
__device__ __forceinline__ uint32_t elect_one() {
    uint32_t pred;
    asm volatile("{\n\t.reg .pred p;\n\telect.sync _|p, 0xFFFFFFFF;\n\t"
                 "selp.b32 %0, 1, 0, p;\n\t}" : "=r"(pred));
    return pred;
}
__device__ __forceinline__ void mbar_wait(uint32_t mbar, uint32_t parity) {
    asm volatile(
        "{\n\t.reg .pred P1;\n\t"
        "W_%=:\n\t"
        "mbarrier.try_wait.parity.acquire.cta.shared::cta.b64 P1, [%0], %1, 0x989680;\n\t"
        "@P1 bra.uni D_%=;\n\t"
        "bra.uni W_%=;\n\t"
        "D_%=:\n\t}"
        :: "r"(mbar), "r"(parity) : "memory");
}
__device__ __forceinline__ uint64_t make_desc(uint32_t addr) {
    const uint64_t base =
        (uint64_t(2) << 61) | (uint64_t(1) << 46) | (uint64_t(64) << 32) | (uint64_t(1) << 16);
    return base | ((uint64_t)(addr >> 4) & 0x3FFF);
}
__device__ __forceinline__ void tc_mma_f16(uint32_t d, uint64_t ad, uint64_t bd,
                                           uint32_t idesc, uint32_t en) {
    asm volatile(
        "{\n\t.reg .pred p;\n\t"
        "setp.ne.u32 p, %4, 0;\n\t"
        "tcgen05.mma.cta_group::1.kind::f16 [%0], %1, %2, %3, {%5,%5,%5,%5}, p;\n\t}"
        :: "r"(d), "l"(ad), "l"(bd), "r"(idesc), "r"(en), "r"(0u) : "memory");
}
#define TCG_IDESC ((1u<<4)|((256u/8)<<17)|((128u/16)<<24))
#define EXPECT_TX(mbar, bytes) \
    asm volatile("mbarrier.arrive.expect_tx.shared.b64 _, [%0], %1;" \
                 :: "r"(mbar), "r"(bytes) : "memory")
#define BULK_CP(dst, src, bytes, mbar) \
    asm volatile("cp.async.bulk.shared::cluster.global.mbarrier::complete_tx::bytes " \
                 "[%0], [%1], %2, [%3];" \
                 :: "r"(dst), "l"(src), "r"(bytes), "r"(mbar) : "memory")
#endif

// ---------------------------------------------------------------------------
// Merged txt/img fp16 GEMM, CTA 128(M)x256(N), chunk-major pre-formatted
// operands (64-k chunks), bulk-DMA pipeline (2 stages), TMEM accumulator.
// EPI: 0 bias -> fp32 row-major; 1 gelu(bias) -> fp16 A-layout (rows=LTOT);
//      2 resid + gate*(bias) -> fp32 row-major; 3 bias -> fp16 row-major.
// ---------------------------------------------------------------------------
template <int EPI>
__global__ void __launch_bounds__(256)
tc_gemm(const __half* __restrict__ A,
        const __half* __restrict__ Bt, const __half* __restrict__ Bi,
        const float* __restrict__ biast, const float* __restrict__ biasi,
        float* __restrict__ Ct, float* __restrict__ Ci, __half* __restrict__ Ch,
        int K, int lda, int ldb, int ldc,
        const float* __restrict__ gatet, const float* __restrict__ gatei,
        const float* __restrict__ residt, const float* __restrict__ residi,
        int ldres) {
    extern __shared__ char smem[];
    const int t = threadIdx.x;
    const int wid = t >> 5, lane = t & 31;
    const int mi = blockIdx.x % NMALL;
    const int m0 = mi * 128;
    const int n0 = (blockIdx.x / NMALL) * 256;
    const bool is_txt = (mi < NMT);
    const __half* B    = is_txt ? Bt : Bi;
    const float* bias  = is_txt ? biast : biasi;
    const float* gate  = is_txt ? gatet : gatei;
    const float* resid = is_txt ? residt : residi;
    float* C           = is_txt ? Ct : Ci;
    const int nc = K / 64;

#if HAS_TCGEN05
    const uint32_t smem_base = smem_u32(smem);
    const uint32_t sA0 = (smem_base + 64 + 1023) & ~1023u;
    const uint32_t sB0 = sA0 + 16384;
    const uint32_t sA1 = sB0 + 32768;
    const uint32_t sB1 = sA1 + 16384;
    const uint32_t tx0 = smem_base + 16, tx1 = smem_base + 24;
    const uint32_t mm0 = smem_base + 32, mm1 = smem_base + 40;
    const uint32_t dn  = smem_base + 48;
    float* sEp = (float*)(smem + (sA0 - smem_base));

    if (wid == 0) {
        asm volatile("tcgen05.alloc.cta_group::1.sync.aligned.shared::cta.b32 [%0], %1;"
                     :: "r"(smem_base), "r"(256u) : "memory");
        asm volatile("tcgen05.relinquish_alloc_permit.cta_group::1.sync.aligned;");
    }
    if (t == 0) {
        asm volatile("mbarrier.init.shared.b64 [%0], 1;" :: "r"(tx0) : "memory");
        asm volatile("mbarrier.init.shared.b64 [%0], 1;" :: "r"(tx1) : "memory");
        asm volatile("mbarrier.init.shared.b64 [%0], 1;" :: "r"(mm0) : "memory");
        asm volatile("mbarrier.init.shared.b64 [%0], 1;" :: "r"(mm1) : "memory");
        asm volatile("mbarrier.init.shared.b64 [%0], 1;" :: "r"(dn)  : "memory");
    }
    __syncthreads();
    uint32_t tmem;
    asm volatile("ld.shared.b32 %0, [%1];" : "=r"(tmem) : "r"(smem_base));

    if (wid == 0 && elect_one()) {
        const __half* Ab = A + (size_t)m0 * 64;
        const __half* Bb = B + (size_t)n0 * 64;
        EXPECT_TX(tx0, 49152u);
        BULK_CP(sA0, Ab, 16384u, tx0);
        BULK_CP(sB0, Bb, 32768u, tx0);
        EXPECT_TX(tx1, 49152u);
        BULK_CP(sA1, Ab + (size_t)lda * 64, 16384u, tx1);
        BULK_CP(sB1, Bb + (size_t)ldb * 64, 32768u, tx1);
        asm volatile("tcgen05.fence::after_thread_sync;" ::: "memory");

        int phtx0 = 0, phtx1 = 0, phmm0 = 0, phmm1 = 0;
        for (int c = 0; c < nc; c++) {
            const int s = c & 1;
            if (s == 0) { mbar_wait(tx0, phtx0); phtx0 ^= 1; }
            else        { mbar_wait(tx1, phtx1); phtx1 ^= 1; }
            uint64_t ad = make_desc(s ? sA1 : sA0);
            uint64_t bd = make_desc(s ? sB1 : sB0);
            #pragma unroll
            for (int ks = 0; ks < 4; ks++)
                tc_mma_f16(tmem, ad + 2 * ks, bd + 2 * ks, TCG_IDESC,
                           (uint32_t)((c > 0) | (ks > 0)));
            asm volatile(
                "tcgen05.commit.cta_group::1.mbarrier::arrive::one.shared::cluster.b64 [%0];"
                :: "r"(s ? mm1 : mm0) : "memory");
            if (c == nc - 1) {
                asm volatile(
                    "tcgen05.commit.cta_group::1.mbarrier::arrive::one.shared::cluster.b64 [%0];"
                    :: "r"(dn) : "memory");
            }
            if (c + 2 < nc) {
                if (s == 0) { mbar_wait(mm0, phmm0); phmm0 ^= 1; }
                else        { mbar_wait(mm1, phmm1); phmm1 ^= 1; }
                const uint32_t txm = s ? tx1 : tx0;
                EXPECT_TX(txm, 49152u);
                BULK_CP(s ? sA1 : sA0, Ab + (size_t)(c + 2) * lda * 64, 16384u, txm);
                BULK_CP(s ? sB1 : sB0, Bb + (size_t)(c + 2) * ldb * 64, 32768u, txm);
            }
        }
    }
    mbar_wait(dn, 0);
    asm volatile("tcgen05.fence::after_thread_sync;" ::: "memory");
    __syncthreads();

    // ---- epilogue: TMEM -> smem bounce (pitch 65) -> coalesced stores ----
    const int half = wid >> 2;
    const int rrow = (wid & 3) * 32 + lane;
    const int f = t & 15, rg = t >> 4;
    for (int cb = 0; cb < 4; cb++) {
        uint32_t r_[32];
        asm volatile(
            "tcgen05.ld.sync.aligned.32x32b.x32.b32 "
            "{%0,%1,%2,%3,%4,%5,%6,%7,%8,%9,%10,%11,%12,%13,%14,%15,"
            "%16,%17,%18,%19,%20,%21,%22,%23,%24,%25,%26,%27,%28,%29,%30,%31}, [%32];"
            : "=r"(r_[0]),"=r"(r_[1]),"=r"(r_[2]),"=r"(r_[3]),
              "=r"(r_[4]),"=r"(r_[5]),"=r"(r_[6]),"=r"(r_[7]),
              "=r"(r_[8]),"=r"(r_[9]),"=r"(r_[10]),"=r"(r_[11]),
              "=r"(r_[12]),"=r"(r_[13]),"=r"(r_[14]),"=r"(r_[15]),
              "=r"(r_[16]),"=r"(r_[17]),"=r"(r_[18]),"=r"(r_[19]),
              "=r"(r_[20]),"=r"(r_[21]),"=r"(r_[22]),"=r"(r_[23]),
              "=r"(r_[24]),"=r"(r_[25]),"=r"(r_[26]),"=r"(r_[27]),
              "=r"(r_[28]),"=r"(r_[29]),"=r"(r_[30]),"=r"(r_[31])
            : "r"(tmem + half * 128 + cb * 32));
        asm volatile("tcgen05.wait::ld.sync.aligned;" ::: "memory");
        #pragma unroll
        for (int j = 0; j < 32; j++)
            sEp[rrow * 65 + half * 32 + j] = __uint_as_float(r_[j]);
        __syncthreads();

        const int scol = (f >> 3) * 32 + (f & 7) * 4;
        const int gcol = n0 + (f >> 3) * 128 + cb * 32 + (f & 7) * 4;
        const float4 bv = *(const float4*)(bias + gcol);
        float4 gv = make_float4(0.f, 0.f, 0.f, 0.f);
        if (EPI == 2) gv = *(const float4*)(gate + gcol);
        #pragma unroll
        for (int i = 0; i < 8; i++) {
            int r = rg + 16 * i;
            int m = m0 + r;
            const float* sp = &sEp[r * 65 + scol];
            float4 v = make_float4(sp[0], sp[1], sp[2], sp[3]);
            v.x += bv.x; v.y += bv.y; v.z += bv.z; v.w += bv.w;
            if (EPI == 1) {
                v.x = gelu_tanh(v.x); v.y = gelu_tanh(v.y);
                v.z = gelu_tanh(v.z); v.w = gelu_tanh(v.w);
                size_t ad2 = ((size_t)(gcol >> 6) * LTOT + m) * 64 +
                             (((((gcol >> 3) & 7) ^ (m & 7)) << 3) + (gcol & 7));
                __half2 ha = __floats2half2_rn(v.x, v.y);
                __half2 hb = __floats2half2_rn(v.z, v.w);
                *(uint2*)(Ch + ad2) = make_uint2(*(unsigned int*)&ha, *(unsigned int*)&hb);
            } else if (EPI == 3) {
                __half2 ha = __floats2half2_rn(v.x, v.y);
                __half2 hb = __floats2half2_rn(v.z, v.w);
                *(uint2*)(Ch + (size_t)m * ldc + gcol) =
                    make_uint2(*(unsigned int*)&ha, *(unsigned int*)&hb);
            } else {
                if (EPI == 2) {
                    float4 rr = *(const float4*)(resid + (size_t)m * ldres + gcol);
                    v.x = rr.x + gv.x * v.x; v.y = rr.y + gv.y * v.y;
                    v.z = rr.z + gv.z * v.z; v.w = rr.w + gv.w * v.w;
                }
                *(float4*)(C + (size_t)m * ldc + gcol) = v;
            }
        }
        __syncthreads();
    }
    if (wid == 0) {
        asm volatile("tcgen05.dealloc.cta_group::1.sync.aligned.b32 %0, %1;"
                     :: "r"(tmem), "r"(256u));
    }
#else
    for (int e = t; e < 128 * 256; e += 256) {
        int r = e >> 8, j = e & 255;
        int m = m0 + r, n = n0 + j;
        float acc = 0.f;
        for (int k = 0; k < K; k++) {
            float a = __half2float(A[aoff16(m, k, lda)]);
            float b = __half2float(B[aoff16(n, k, ldb)]);
            acc += a * b;
        }
        acc += bias[n];
        if (EPI == 1) {
            acc = gelu_tanh(acc);
            Ch[aoff16(m, n, LTOT)] = __float2half_rn(acc);
        } else if (EPI == 3) {
            Ch[(size_t)m * ldc + n] = __float2half_rn(acc);
        } else {
            if (EPI == 2) acc = resid[(size_t)m * ldres + n] + gate[n] * acc;
            C[(size_t)m * ldc + n] = acc;
        }
    }
#endif
}

// ---------------------------------------------------------------------------
// fp16 flash attention (unchanged from R13, known good)
// ---------------------------------------------------------------------------
#define KPITCH 136
#define PPITCH 72
#define SK_OFF 0
#define SV_OFF (64 * KPITCH)
#define SP_OFF (2 * 64 * KPITCH)
#define FA_SMEM_BYTES ((2 * 64 * KPITCH + 8 * 16 * PPITCH) * 2)

__global__ void __launch_bounds__(256, 1)
flash_attn(const __half* __restrict__ Q, const __half* __restrict__ K,
           const __half* __restrict__ V, __half* __restrict__ O) {
    extern __shared__ __half smh[];
    __half* sK = smh + SK_OFF;
    __half* sV = smh + SV_OFF;
    __half* sP = smh + SP_OFF;

    const int t = threadIdx.x;
    const int wid = t >> 5, lane = t & 31;
    const int gid = lane >> 2, tig = lane & 3;
    const int h = blockIdx.y;
    const int q0 = blockIdx.x * 128;
    const int m0 = wid * 16;
    __half* sPw = sP + wid * 16 * PPITCH;

    const __half* Qh = Q + ((size_t)h * LTOT + q0) * HD;
    const __half* Kh = K + (size_t)h * LTOT * HD;
    const __half* Vh = V + (size_t)h * LTOT * HD;

    unsigned int qf[8][4];
    #pragma unroll
    for (int kb = 0; kb < 8; kb++) {
        const __half* qr = Qh + (size_t)(m0 + gid) * HD + kb * 16 + 2 * tig;
        qf[kb][0] = *(const unsigned int*)(qr);
        qf[kb][1] = *(const unsigned int*)(qr + 8 * HD);
        qf[kb][2] = *(const unsigned int*)(qr + 8);
        qf[kb][3] = *(const unsigned int*)(qr + 8 * HD + 8);
    }

    float co[16][4];
    #pragma unroll
    for (int i = 0; i < 16; i++)
        #pragma unroll
        for (int j = 0; j < 4; j++) co[i][j] = 0.0f;
    float mrow0 = -1e30f, mrow1 = -1e30f, lrow0 = 0.0f, lrow1 = 0.0f;

    for (int kv = 0; kv < LTOT; kv += 64) {
        __syncthreads();
        {
            const int c = t >> 2;
            const int dseg = (t & 3) * 32;
            const __half* kr = Kh + (size_t)(kv + c) * HD + dseg;
            const __half* vr = Vh + (size_t)(kv + c) * HD + dseg;
            #pragma unroll
            for (int i = 0; i < 4; i++)
                *(uint4*)(sK + c * KPITCH + dseg + i * 8) = *(const uint4*)(kr + i * 8);
            #pragma unroll
            for (int i = 0; i < 4; i++)
                *(uint4*)(sV + c * KPITCH + dseg + i * 8) = *(const uint4*)(vr + i * 8);
        }
        __syncthreads();

        float cs[8][4];
        #pragma unroll
        for (int i = 0; i < 8; i++)
            #pragma unroll
            for (int j = 0; j < 4; j++) cs[i][j] = 0.0f;
        #pragma unroll
        for (int kb = 0; kb < 8; kb++) {
            #pragma unroll
            for (int nt = 0; nt < 8; nt++) {
                const __half* kp = sK + (nt * 8 + gid) * KPITCH + kb * 16 + 2 * tig;
                unsigned int b0 = *(const unsigned int*)(kp);
                unsigned int b1 = *(const unsigned int*)(kp + 8);
                mma_f16(cs[nt], qf[kb], b0, b1);
            }
        }

        float rmax0 = -1e30f, rmax1 = -1e30f;
        #pragma unroll
        for (int nt = 0; nt < 8; nt++) {
            rmax0 = fmaxf(rmax0, fmaxf(cs[nt][0], cs[nt][1]));
            rmax1 = fmaxf(rmax1, fmaxf(cs[nt][2], cs[nt][3]));
        }
        rmax0 = fmaxf(rmax0, __shfl_xor_sync(0xffffffffu, rmax0, 1));
        rmax0 = fmaxf(rmax0, __shfl_xor_sync(0xffffffffu, rmax0, 2));
        rmax1 = fmaxf(rmax1, __shfl_xor_sync(0xffffffffu, rmax1, 1));
        rmax1 = fmaxf(rmax1, __shfl_xor_sync(0xffffffffu, rmax1, 2));
        float mn0 = fmaxf(mrow0, rmax0);
        float mn1 = fmaxf(mrow1, rmax1);
        float corr0 = __expf(mrow0 - mn0);
        float corr1 = __expf(mrow1 - mn1);
        mrow0 = mn0; mrow1 = mn1;

        float rs0 = 0.0f, rs1 = 0.0f;
        #pragma unroll
        for (int nt = 0; nt < 8; nt++) {
            cs[nt][0] = __expf(cs[nt][0] - mn0);
            cs[nt][1] = __expf(cs[nt][1] - mn0);
            cs[nt][2] = __expf(cs[nt][2] - mn1);
            cs[nt][3] = __expf(cs[nt][3] - mn1);
            rs0 += cs[nt][0] + cs[nt][1];
            rs1 += cs[nt][2] + cs[nt][3];
        }
        rs0 += __shfl_xor_sync(0xffffffffu, rs0, 1);
        rs0 += __shfl_xor_sync(0xffffffffu, rs0, 2);
        rs1 += __shfl_xor_sync(0xffffffffu, rs1, 1);
        rs1 += __shfl_xor_sync(0xffffffffu, rs1, 2);
        lrow0 = lrow0 * corr0 + rs0;
        lrow1 = lrow1 * corr1 + rs1;

        #pragma unroll
        for (int nt = 0; nt < 16; nt++) {
            co[nt][0] *= corr0; co[nt][1] *= corr0;
            co[nt][2] *= corr1; co[nt][3] *= corr1;
        }

        #pragma unroll
        for (int nt = 0; nt < 8; nt++) {
            __half2 p01 = __floats2half2_rn(cs[nt][0], cs[nt][1]);
            __half2 p23 = __floats2half2_rn(cs[nt][2], cs[nt][3]);
            *(unsigned int*)(sPw + gid * PPITCH + nt * 8 + 2 * tig) = *(unsigned int*)&p01;
            *(unsigned int*)(sPw + (gid + 8) * PPITCH + nt * 8 + 2 * tig) = *(unsigned int*)&p23;
        }
        __syncwarp();

        unsigned int pf[4][4];
        #pragma unroll
        for (int kb = 0; kb < 4; kb++) {
            const __half* pp = sPw + gid * PPITCH + kb * 16 + 2 * tig;
            pf[kb][0] = *(const unsigned int*)(pp);
            pf[kb][1] = *(const unsigned int*)(pp + 8 * PPITCH);
            pf[kb][2] = *(const unsigned int*)(pp + 8);
            pf[kb][3] = *(const unsigned int*)(pp + 8 * PPITCH + 8);
        }

        #pragma unroll
        for (int nt = 0; nt < 16; nt++) {
            #pragma unroll
            for (int cb = 0; cb < 2; cb++) {
                uint32_t va = smem_u32(sV + (cb * 32 + lane) * KPITCH + nt * 8);
                unsigned int v0, v1, v2, v3;
                asm volatile(
                    "ldmatrix.sync.aligned.m8n8.x4.trans.shared.b16 {%0,%1,%2,%3}, [%4];"
                    : "=r"(v0), "=r"(v1), "=r"(v2), "=r"(v3) : "r"(va));
                mma_f16(co[nt], pf[cb * 2 + 0], v0, v1);
                mma_f16(co[nt], pf[cb * 2 + 1], v2, v3);
            }
        }
    }

    float inv0 = 1.0f / lrow0;
    float inv1 = 1.0f / lrow1;
    int ra = q0 + m0 + gid;
    int rb = ra + 8;
    #pragma unroll
    for (int nt = 0; nt < 16; nt++) {
        int col = h * HD + nt * 8 + tig * 2;
        int q = (col >> 3) & 7, e = col & 7;
        size_t base = (size_t)(col >> 6) * LTOT * 64;
        __half2 va = __floats2half2_rn(co[nt][0] * inv0, co[nt][1] * inv0);
        __half2 vb = __floats2half2_rn(co[nt][2] * inv1, co[nt][3] * inv1);
        *(unsigned int*)(O + base + (size_t)ra * 64 + ((q ^ (ra & 7)) << 3) + e) =
            *(unsigned int*)&va;
        *(unsigned int*)(O + base + (size_t)rb * 64 + ((q ^ (rb & 7)) << 3) + e) =
            *(unsigned int*)&vb;
    }
}

// ---------------------------------------------------------------------------
// Host launcher
// ---------------------------------------------------------------------------
static void tc_launch(int epi, const __half* A,
                      const __half* Bt, const __half* Bi,
                      const float* biast, const float* biasi,
                      float* Ct, float* Ci, __half* Ch,
                      int N, int K, int lda, int ldb, int ldc,
                      const float* gatet = nullptr, const float* gatei = nullptr,
                      const float* residt = nullptr, const float* residi = nullptr,
                      int ldres = 0) {
    dim3 grid(NMALL * (N / 256));
    if (epi == 0)
        tc_gemm<0><<<grid, 256, TCG_SMEM_BYTES>>>(A, Bt, Bi, biast, biasi, Ct, Ci, Ch,
                                                  K, lda, ldb, ldc, gatet, gatei, residt, residi, ldres);
    else if (epi == 1)
        tc_gemm<1><<<grid, 256, TCG_SMEM_BYTES>>>(A, Bt, Bi, biast, biasi, Ct, Ci, Ch,
                                                  K, lda, ldb, ldc, gatet, gatei, residt, residi, ldres);
    else if (epi == 2)
        tc_gemm<2><<<grid, 256, TCG_SMEM_BYTES>>>(A, Bt, Bi, biast, biasi, Ct, Ci, Ch,
                                                  K, lda, ldb, ldc, gatet, gatei, residt, residi, ldres);
    else
        tc_gemm<3><<<grid, 256, TCG_SMEM_BYTES>>>(A, Bt, Bi, biast, biasi, Ct, Ci, Ch,
                                                  K, lda, ldb, ldc, gatet, gatei, residt, residi, ldres);
}

extern "C" void kernel_launch(void* const* d_in, const int* in_sizes, int n_in,
                              void* d_out, int out_size) {
    const float* img        = (const float*)d_in[0];
    const float* txt        = (const float*)d_in[1];
    const float* vec        = (const float*)d_in[2];
    const float* pe         = (const float*)d_in[3];
    const float* img_mod_w  = (const float*)d_in[4];
    const float* img_mod_b  = (const float*)d_in[5];
    const float* img_qkv_w  = (const float*)d_in[6];
    const float* img_qkv_b  = (const float*)d_in[7];
    const float* img_q_s    = (const float*)d_in[8];
    const float* img_k_s    = (const float*)d_in[9];
    const float* img_proj_w = (const float*)d_in[10];
    const float* img_proj_b = (const float*)d_in[11];
    const float* img_mlp_w1 = (const float*)d_in[12];
    const float* img_mlp_b1 = (const float*)d_in[13];
    const float* img_mlp_w2 = (const float*)d_in[14];
    const float* img_mlp_b2 = (const float*)d_in[15];
    const float* txt_mod_w  = (const float*)d_in[16];
    const float* txt_mod_b  = (const float*)d_in[17];
    const float* txt_qkv_w  = (const float*)d_in[18];
    const float* txt_qkv_b  = (const float*)d_in[19];
    const float* txt_q_s    = (const float*)d_in[20];
    const float* txt_k_s    = (const float*)d_in[21];
    const float* txt_proj_w = (const float*)d_in[22];
    const float* txt_proj_b = (const float*)d_in[23];
    const float* txt_mlp_w1 = (const float*)d_in[24];
    const float* txt_mlp_b1 = (const float*)d_in[25];
    const float* txt_mlp_w2 = (const float*)d_in[26];
    const float* txt_mlp_b2 = (const float*)d_in[27];
    float* out = (float*)d_out;

    float *sv, *modi, *modt, *x1;
    __half *x, *attn, *x2, *h1, *w, *q, *k, *v, *qkvb;
    cudaGetSymbolAddress((void**)&sv,   g_silu);
    cudaGetSymbolAddress((void**)&modi, g_mod_img);
    cudaGetSymbolAddress((void**)&modt, g_mod_txt);
    cudaGetSymbolAddress((void**)&x,    g_x);
    cudaGetSymbolAddress((void**)&qkvb, g_qkv);
    cudaGetSymbolAddress((void**)&q,    g_q);
    cudaGetSymbolAddress((void**)&k,    g_k);
    cudaGetSymbolAddress((void**)&v,    g_v);
    cudaGetSymbolAddress((void**)&attn, g_attn);
    cudaGetSymbolAddress((void**)&x1,   g_x1);
    cudaGetSymbolAddress((void**)&x2,   g_x2);
    cudaGetSymbolAddress((void**)&h1,   g_h1);
    cudaGetSymbolAddress((void**)&w,    g_w);

    cudaFuncSetAttribute(flash_attn, cudaFuncAttributeMaxDynamicSharedMemorySize, FA_SMEM_BYTES);
    cudaFuncSetAttribute(tc_gemm<0>, cudaFuncAttributeMaxDynamicSharedMemorySize, TCG_SMEM_BYTES);
    cudaFuncSetAttribute(tc_gemm<1>, cudaFuncAttributeMaxDynamicSharedMemorySize, TCG_SMEM_BYTES);
    cudaFuncSetAttribute(tc_gemm<2>, cudaFuncAttributeMaxDynamicSharedMemorySize, TCG_SMEM_BYTES);
    cudaFuncSetAttribute(tc_gemm<3>, cudaFuncAttributeMaxDynamicSharedMemorySize, TCG_SMEM_BYTES);

    // weight conversion (chunk-major fp16, pre-swizzled), 4 blocks per chunk
    conv_w<<<dim3(QKVW / 256, HS / 16),   256>>>(txt_qkv_w,  w + OFF_QKV_T,  QKVW);
    conv_w<<<dim3(QKVW / 256, HS / 16),   256>>>(img_qkv_w,  w + OFF_QKV_I,  QKVW);
    conv_w<<<dim3(HS / 256,   HS / 16),   256>>>(txt_proj_w, w + OFF_PROJ_T, HS);
    conv_w<<<dim3(HS / 256,   HS / 16),   256>>>(img_proj_w, w + OFF_PROJ_I, HS);
    conv_w<<<dim3(MLPD / 256, HS / 16),   256>>>(txt_mlp_w1, w + OFF_MLP1_T, MLPD);
    conv_w<<<dim3(MLPD / 256, HS / 16),   256>>>(img_mlp_w1, w + OFF_MLP1_I, MLPD);
    conv_w<<<dim3(HS / 256,   MLPD / 16), 256>>>(txt_mlp_w2, w + OFF_MLP2_T, HS);
    conv_w<<<dim3(HS / 256,   MLPD / 16), 256>>>(img_mlp_w2, w + OFF_MLP2_I, HS);

    silu_kernel<<<HS / 256, 256>>>(vec, sv);
    mod_gemv2<<<(6 * HS) / 64, 256>>>(sv, img_mod_w, img_mod_b, modi);
    mod_gemv2<<<(6 * HS) / 64, 256>>>(sv, txt_mod_w, txt_mod_b, modt);

    ln_mod<<<LTXT, 256>>>(txt, x, modt + 0 * HS, modt + 1 * HS, 0);
    ln_mod<<<LIMG, 256>>>(img, x, modi + 0 * HS, modi + 1 * HS, LTXT);

    // QKV (merged txt/img) -> fp16 row-major qkvb
    tc_launch(3, x, w + OFF_QKV_T, w + OFF_QKV_I, txt_qkv_b, img_qkv_b,
              nullptr, nullptr, qkvb, QKVW, HS, LTOT, QKVW, QKVW);

    rms_rope<<<LTOT, 256>>>(qkvb, pe, txt_q_s, txt_k_s, img_q_s, img_k_s, q, k, v);

    {
        dim3 fgrid(LTOT / 128, NH);
        flash_attn<<<fgrid, 256, FA_SMEM_BYTES>>>(q, k, v, attn);
    }

    // proj + gated residual (merged) -> row-major fp32 x1
    tc_launch(2, attn, w + OFF_PROJ_T, w + OFF_PROJ_I, txt_proj_b, img_proj_b,
              x1, x1, nullptr, HS, HS, LTOT, HS, HS,
              modt + 2 * HS, modi + 2 * HS,
              txt, img - (size_t)LTXT * HS, HS);

    ln_mod<<<LTXT, 256>>>(x1, x2,                     modt + 3 * HS, modt + 4 * HS, 0);
    ln_mod<<<LIMG, 256>>>(x1 + (size_t)LTXT * HS, x2, modi + 3 * HS, modi + 4 * HS, LTXT);

    // MLP1 (+GELU, merged) -> fp16 A-layout h1
    tc_launch(1, x2, w + OFF_MLP1_T, w + OFF_MLP1_I, txt_mlp_b1, img_mlp_b1,
              nullptr, nullptr, h1, MLPD, HS, LTOT, MLPD, MLPD);

    // MLP2 (+gated residual, merged) -> d_out (img first, then txt)
    tc_launch(2, h1, w + OFF_MLP2_T, w + OFF_MLP2_I, txt_mlp_b2, img_mlp_b2,
              out + (size_t)LIMG * HS,
              out - (size_t)LTXT * HS,
              nullptr, HS, MLPD, LTOT, HS, HS,
              modt + 5 * HS, modi + 5 * HS,
              x1, x1, HS);
}